// round 1
// baseline (speedup 1.0000x reference)
#include <cuda_runtime.h>
#include <cuda_bf16.h>
#include <cstdint>

// out[b,i,j,d] = S[x[b,i]][x[b,j]][d]
// S[v1][v2][d] = (table[v1] @ W[:128])[d] + (table[v2] @ W[128:])[d] + b[d]
// VOCAB=8, EMB=128, B=4, L=512  -> out = 4*512*512*128 f32 = 512 MiB (store-bound)

#define VOCAB 8
#define EMB   128
#define BATCH 4
#define SEQL  512

// 8*8*128 floats = 2048 float4 = 32 KB LUT (device scratch; no allocation)
__device__ float4 g_S4[VOCAB * VOCAB * (EMB / 4)];

// ---------------------------------------------------------------------------
// Kernel 1: build the LUT. One block, 1024 threads. Tiny (~0.5M MACs).
// ---------------------------------------------------------------------------
__global__ void build_lut_kernel(const float* __restrict__ table,
                                 const float* __restrict__ W,
                                 const float* __restrict__ bias) {
    __shared__ float Psh[2 * VOCAB * EMB];   // P[p][v][d], 8 KB
    __shared__ float tsh[VOCAB * EMB];       // table, 4 KB

    const int tid = threadIdx.x;             // 1024 threads

    // stage table into shared (8*128 = 1024 elements)
    tsh[tid] = table[tid];
    __syncthreads();

    // Each thread computes 2 dot products of length 128.
    // e = p*1024 + v*128 + d ; consecutive tid -> consecutive d -> coalesced W loads
    #pragma unroll
    for (int e = tid; e < 2 * VOCAB * EMB; e += 1024) {
        const int p = e >> 10;
        const int v = (e >> 7) & 7;
        const int d = e & 127;
        const float* wp = W + p * EMB * EMB + d;   // column d of W-half p
        const float* tp = tsh + v * EMB;
        float acc = 0.0f;
        #pragma unroll 8
        for (int k = 0; k < EMB; k++) acc += tp[k] * wp[k * EMB];
        Psh[e] = acc;
    }
    __syncthreads();

    // Assemble S[v1][v2][d] = P1[v1][d] + P2[v2][d] + b[d]  (8192 elems)
    float* gS = reinterpret_cast<float*>(g_S4);
    #pragma unroll
    for (int e = tid; e < VOCAB * VOCAB * EMB; e += 1024) {
        const int v1 = e >> 10;
        const int v2 = (e >> 7) & 7;
        const int d  = e & 127;
        gS[e] = Psh[v1 * EMB + d] + Psh[VOCAB * EMB + v2 * EMB + d] + bias[d];
    }
}

// ---------------------------------------------------------------------------
// Kernel 2: stream 512 MiB of output. One block per (b,i): 2048 blocks x 256t.
// Per block: 512 j's x 32 float4 = 16384 float4 stores (256 KB).
// Warp granularity: each warp iteration covers exactly one j (idx>>5 constant
// within warp), so xs[j] is a shared broadcast and s4 read is LDS.128
// conflict-free. Stores are fully coalesced STG.128 with .cs streaming hint.
// ---------------------------------------------------------------------------
__global__ __launch_bounds__(256) void write_out_kernel(
        const int* __restrict__ x, float4* __restrict__ out) {
    __shared__ float4 s4[VOCAB * (EMB / 4)];   // S[v1][ : ][ : ] slice, 4 KB
    __shared__ int    xs[SEQL];                // x row of this batch, 2 KB

    const int row = blockIdx.x;                // 0..2047  (b*512 + i)
    const int bb  = row >> 9;                  // batch
    const int tid = threadIdx.x;               // 256

    // stage x[bb][:]
    xs[tid]       = x[(bb << 9) + tid];
    xs[tid + 256] = x[(bb << 9) + tid + 256];

    // stage S[v1] : 8*128 floats = 256 float4
    const int v1 = x[row];
    const float4* src = g_S4 + v1 * (VOCAB * EMB / 4);
    s4[tid] = src[tid];
    __syncthreads();

    float4* outp = out + (size_t)row * (SEQL * EMB / 4);

    #pragma unroll 8
    for (int it = 0; it < 64; it++) {
        const int idx = (it << 8) + tid;       // 0..16383
        const int j   = idx >> 5;              // constant within a warp
        const int c   = idx & 31;
        const float4 v = s4[(xs[j] << 5) + c];
        __stcs(outp + idx, v);                 // streaming store, evict-first
    }
}

// ---------------------------------------------------------------------------
// Launch. Inputs (metadata order): x int32[2048], table f32[1024],
// W f32[32768], b f32[128]. Output: f32[134217728].
// ---------------------------------------------------------------------------
extern "C" void kernel_launch(void* const* d_in, const int* in_sizes, int n_in,
                              void* d_out, int out_size) {
    const int*   x     = (const int*)  d_in[0];
    const float* table = (const float*)d_in[1];
    const float* W     = (const float*)d_in[2];
    const float* bias  = (const float*)d_in[3];
    float4*      out   = (float4*)d_out;

    build_lut_kernel<<<1, 1024>>>(table, W, bias);
    write_out_kernel<<<BATCH * SEQL, 256>>>(x, out);
}

// round 2
// speedup vs baseline: 1.0434x; 1.0434x over previous
#include <cuda_runtime.h>
#include <cuda_bf16.h>
#include <cstdint>

// out[b,i,j,d] = P1[x[b,i]][d] + P2b[x[b,j]][d]
//   P1[v]  = table[v] @ W[:128]
//   P2b[v] = table[v] @ W[128:] + bias
// VOCAB=8, EMB=128, B=4, L=512 -> out = 512 MiB f32 (pure store-roofline)

#define VOCAB 8
#define EMB   128
#define BATCH 4
#define SEQL  512

// P[p][v][d] : 2*8*128 floats = 8 KB device scratch (bias folded into p=1)
__device__ float g_P[2 * VOCAB * EMB];

// ---------------------------------------------------------------------------
// Kernel 1: compute P. 2 blocks (one per W-half) x 1024 threads
// (one thread per output element). Unrolled len-128 dot for MLP.
// ---------------------------------------------------------------------------
__global__ __launch_bounds__(1024) void build_p_kernel(
        const float* __restrict__ table,
        const float* __restrict__ W,
        const float* __restrict__ bias) {
    __shared__ float tsh[VOCAB * EMB];       // 4 KB table stage

    const int p   = blockIdx.x;              // 0..1 (W half)
    const int tid = threadIdx.x;             // 0..1023

    tsh[tid] = table[tid];
    __syncthreads();

    const int v = tid >> 7;
    const int d = tid & 127;
    const float* __restrict__ wp = W + p * EMB * EMB + d;  // column d of half p
    const float* __restrict__ tp = tsh + v * EMB;

    float acc = (p == 1) ? bias[d] : 0.0f;
    #pragma unroll 16
    for (int k = 0; k < EMB; k++) acc += tp[k] * wp[k * EMB];

    g_P[p * (VOCAB * EMB) + tid] = acc;
}

// ---------------------------------------------------------------------------
// Kernel 2: stream 512 MiB. One block per (b,i): 2048 blocks x 256 threads.
// Block assembles its S[v1] slice (8 v2 x 32 float4) in shared from P, then
// emits 64 iterations of fully-coalesced STG.128 (.cs streaming).
// Each warp-iteration covers exactly one j: xs[j] is a broadcast, s4 read is
// conflict-free LDS.128.
// ---------------------------------------------------------------------------
__global__ __launch_bounds__(256) void write_out_kernel(
        const int* __restrict__ x, float4* __restrict__ out) {
    __shared__ float4 s4[VOCAB * (EMB / 4)]; // 4 KB: S[v1][v2][d]
    __shared__ int    xs[SEQL];              // 2 KB: x row of this batch

    const int row = blockIdx.x;              // b*512 + i
    const int bb  = row >> 9;
    const int tid = threadIdx.x;

    // stage x[bb][:]
    xs[tid]       = x[(bb << 9) + tid];
    xs[tid + 256] = x[(bb << 9) + tid + 256];

    // assemble S[v1] slice: s4[v2*32+c] = P1[v1][c] + P2b[v2][c]
    const int v1 = x[row];                   // L2-hot
    const int v2 = tid >> 5;
    const int c  = tid & 31;
    const float4* __restrict__ P4 = (const float4*)g_P;
    const float4 a  = P4[(v1 << 5) + c];                   // P1[v1]
    const float4 pb = P4[(VOCAB << 5) + (v2 << 5) + c];    // P2b[v2]
    s4[tid] = make_float4(a.x + pb.x, a.y + pb.y, a.z + pb.z, a.w + pb.w);
    __syncthreads();

    float4* __restrict__ outp = out + (size_t)row * (SEQL * EMB / 4);

    #pragma unroll 8
    for (int it = 0; it < 64; it++) {
        const int idx = (it << 8) + tid;     // 0..16383
        const int j   = idx >> 5;            // constant within a warp
        const int cc  = idx & 31;
        const float4 v = s4[(xs[j] << 5) + cc];
        __stcs(outp + idx, v);               // streaming store, evict-first
    }
}

// ---------------------------------------------------------------------------
// Inputs (metadata order): x int32[2048], table f32[1024], W f32[32768],
// b f32[128]. Output: f32[134217728].
// ---------------------------------------------------------------------------
extern "C" void kernel_launch(void* const* d_in, const int* in_sizes, int n_in,
                              void* d_out, int out_size) {
    const int*   x     = (const int*)  d_in[0];
    const float* table = (const float*)d_in[1];
    const float* W     = (const float*)d_in[2];
    const float* bias  = (const float*)d_in[3];
    float4*      out   = (float4*)d_out;

    build_p_kernel<<<2, 1024>>>(table, W, bias);
    write_out_kernel<<<BATCH * SEQL, 256>>>(x, out);
}

// round 3
// speedup vs baseline: 1.0485x; 1.0048x over previous
#include <cuda_runtime.h>
#include <cuda_bf16.h>
#include <cstdint>

// out[b,i,j,d] = P1[x[b,i]][d] + P2b[x[b,j]][d]
//   P1[v]  = table[v] @ W[:128]
//   P2b[v] = table[v] @ W[128:] + bias
// VOCAB=8, EMB=128, B=4, L=512 -> out = 512 MiB f32 (pure store-roofline).
// R3: PDL overlap of build_p with write_out prologue + launch latency.

#define VOCAB 8
#define EMB   128
#define BATCH 4
#define SEQL  512

// P[p][v][d] : 2*8*128 floats = 8 KB device scratch (bias folded into p=1)
__device__ float g_P[2 * VOCAB * EMB];

// ---------------------------------------------------------------------------
// Kernel 1 (PDL primary): compute P. 2 blocks x 1024 threads, one thread per
// dot product (len 128, unrolled for MLP). Triggers dependent launch as soon
// as its stores are fenced.
// ---------------------------------------------------------------------------
__global__ __launch_bounds__(1024) void build_p_kernel(
        const float* __restrict__ table,
        const float* __restrict__ W,
        const float* __restrict__ bias) {
    __shared__ float tsh[VOCAB * EMB];       // 4 KB table stage

    const int p   = blockIdx.x;              // 0..1 (W half)
    const int tid = threadIdx.x;             // 0..1023

    tsh[tid] = table[tid];
    __syncthreads();

    const int v = tid >> 7;
    const int d = tid & 127;
    const float* __restrict__ wp = W + p * EMB * EMB + d;  // column d of half p
    const float* __restrict__ tp = tsh + v * EMB;

    float acc = (p == 1) ? bias[d] : 0.0f;
    #pragma unroll 16
    for (int k = 0; k < EMB; k++) acc += tp[k] * wp[k * EMB];

    g_P[p * (VOCAB * EMB) + tid] = acc;

    // Make P visible, then release the dependent (write) kernel early.
    __threadfence();
    cudaTriggerProgrammaticLaunchCompletion();
}

// ---------------------------------------------------------------------------
// Kernel 2 (PDL secondary): stream 512 MiB. One block per (b,i): 2048 blocks
// x 256 threads. Prologue (xs staging) runs before the grid-dependency sync;
// only the g_P reads wait on the primary. Then 64 iterations of fully
// coalesced STG.128 (.cs streaming); each warp-iteration covers one j so
// xs[j] is a broadcast and the s4 read is conflict-free LDS.128.
// ---------------------------------------------------------------------------
__global__ __launch_bounds__(256) void write_out_kernel(
        const int* __restrict__ x, float4* __restrict__ out) {
    __shared__ float4 s4[VOCAB * (EMB / 4)]; // 4 KB: S[v1][v2][d]
    __shared__ int    xs[SEQL];              // 2 KB: x row of this batch

    const int row = blockIdx.x;              // b*512 + i
    const int bb  = row >> 9;
    const int tid = threadIdx.x;

    // ---- prologue: independent of g_P, overlaps with build_p ----
    xs[tid]       = x[(bb << 9) + tid];
    xs[tid + 256] = x[(bb << 9) + tid + 256];
    const int v1 = x[row];
    const int v2 = tid >> 5;
    const int c  = tid & 31;
    float4* __restrict__ outp = out + (size_t)row * (SEQL * EMB / 4);

    // ---- wait for primary's g_P stores ----
    cudaGridDependencySynchronize();

    // assemble S[v1] slice: s4[v2*32+c] = P1[v1][c] + P2b[v2][c]
    const float4* __restrict__ P4 = (const float4*)g_P;
    const float4 a  = P4[(v1 << 5) + c];                   // P1[v1]
    const float4 pb = P4[(VOCAB << 5) + (v2 << 5) + c];    // P2b[v2]
    s4[tid] = make_float4(a.x + pb.x, a.y + pb.y, a.z + pb.z, a.w + pb.w);
    __syncthreads();

    #pragma unroll 8
    for (int it = 0; it < 64; it++) {
        const int idx = (it << 8) + tid;     // 0..16383
        const int j   = idx >> 5;            // constant within a warp
        const int cc  = idx & 31;
        const float4 v = s4[(xs[j] << 5) + cc];
        __stcs(outp + idx, v);               // streaming store, evict-first
    }
}

// ---------------------------------------------------------------------------
// Inputs (metadata order): x int32[2048], table f32[1024], W f32[32768],
// b f32[128]. Output: f32[134217728].
// ---------------------------------------------------------------------------
extern "C" void kernel_launch(void* const* d_in, const int* in_sizes, int n_in,
                              void* d_out, int out_size) {
    const int*   x     = (const int*)  d_in[0];
    const float* table = (const float*)d_in[1];
    const float* W     = (const float*)d_in[2];
    const float* bias  = (const float*)d_in[3];
    float4*      out   = (float4*)d_out;

    build_p_kernel<<<2, 1024>>>(table, W, bias);

    // Secondary launch with programmatic stream serialization (PDL): may begin
    // before build_p completes; ordering enforced by
    // cudaGridDependencySynchronize() inside the kernel.
    cudaLaunchConfig_t cfg = {};
    cfg.gridDim  = dim3(BATCH * SEQL);
    cfg.blockDim = dim3(256);
    cfg.dynamicSmemBytes = 0;
    cfg.stream = 0;
    cudaLaunchAttribute attr[1];
    attr[0].id = cudaLaunchAttributeProgrammaticStreamSerialization;
    attr[0].val.programmaticStreamSerializationAllowed = 1;
    cfg.attrs = attr;
    cfg.numAttrs = 1;
    cudaLaunchKernelEx(&cfg, write_out_kernel, x, out);
}